// round 10
// baseline (speedup 1.0000x reference)
#include <cuda_runtime.h>
#include <cuda_bf16.h>
#include <cstdint>

// LSTM  B=64, T=1024, D=512, U=512, OUT=4
#define BATCH    64
#define TSTEPS   1024
#define DIN      512
#define UNITS    512
#define FOURU    2048
#define NCTA     128
#define TPB      256
#define NBG      4
#define NMTILE   4096
#define NKSTEP   32

// recurrence smem (floats)
#define SM_R4     0        // [128 kq][16 u][16 e] e=g*4+kl : 32768
#define SM_H4     32768    // 2 bufs x [32 kq][68 pad]      : 4352
#define SM_XZ     37120    // [2][4 g][16 u][17 pad]        : 2176
#define SM_FLOATS 39296
#define SM_BYTES  (SM_FLOATS * 4)   // 157,184 B -> 1 CTA/SM

__device__ float    g_xz[(size_t)BATCH * TSTEPS * FOURU];
__device__ uint4    g_Afrag[(size_t)NMTILE * NKSTEP * 2 * 32];
__device__ uint4    g_Wfrag[(size_t)NKSTEP * 2 * 64 * 32 * 2];
__device__ float    g_hT[2][UNITS][BATCH];      // unit-major
__device__ unsigned g_flag[NBG][32][8];         // 32B-padded monotonic flags

typedef unsigned long long u64t;
__device__ __forceinline__ void ffma2(u64t& d, u64t a, u64t b) {
    asm("fma.rn.f32x2 %0, %1, %2, %0;" : "+l"(d) : "l"(a), "l"(b));
}
__device__ __forceinline__ float2 unpack2(u64t v) {
    float2 f; asm("mov.b64 {%0, %1}, %2;" : "=f"(f.x), "=f"(f.y) : "l"(v)); return f;
}
__device__ __forceinline__ float fsig(float x) {
    return __fdividef(1.f, 1.f + __expf(-x));
}
__device__ __forceinline__ float ftanh(float x) {
    return 1.f - __fdividef(2.f, __expf(2.f * x) + 1.f);
}
__device__ __forceinline__ void st_release(unsigned* p, unsigned v) {
    asm volatile("st.release.gpu.global.u32 [%0], %1;" :: "l"(p), "r"(v) : "memory");
}
__device__ __forceinline__ unsigned ld_acquire(const unsigned* p) {
    unsigned v;
    asm volatile("ld.acquire.gpu.global.u32 %0, [%1];" : "=r"(v) : "l"(p) : "memory");
    return v;
}
__device__ __forceinline__ uint32_t pack_split_hi(float a, float b) {
    __nv_bfloat16 ha = __float2bfloat16(a), hb = __float2bfloat16(b);
    return (uint32_t)*(uint16_t*)&ha | ((uint32_t)*(uint16_t*)&hb << 16);
}
__device__ __forceinline__ uint32_t pack_split_lo(float a, float b) {
    __nv_bfloat16 ha = __float2bfloat16(a), hb = __float2bfloat16(b);
    __nv_bfloat16 la = __float2bfloat16(a - __bfloat162float(ha));
    __nv_bfloat16 lb = __float2bfloat16(b - __bfloat162float(hb));
    return (uint32_t)*(uint16_t*)&la | ((uint32_t)*(uint16_t*)&lb << 16);
}

__global__ void init_kernel() {
    int i = blockIdx.x * blockDim.x + threadIdx.x;
    if (i < 2 * UNITS * BATCH) ((float*)g_hT)[i] = 0.f;
    if (i < NBG * 32 * 8) ((unsigned*)g_flag)[i] = 0u;
}

// ---- prep A ----------------------------------------------------------------
__global__ __launch_bounds__(256) void prep_A(const float* __restrict__ A) {
    int f = blockIdx.x * 256 + threadIdx.x;
    int t = f & 31, ks = (f >> 5) & 31, mt = f >> 10;
    uint32_t hi[4], lo[4];
#pragma unroll
    for (int r = 0; r < 4; r++) {
        int m  = mt * 16 + (r & 1) * 8 + (t >> 2);
        int k0 = ks * 16 + ((r & 2) << 2) + ((t & 3) << 1);
        float2 av = *(const float2*)(A + (size_t)m * DIN + k0);
        hi[r] = pack_split_hi(av.x, av.y);
        lo[r] = pack_split_lo(av.x, av.y);
    }
    size_t ib = ((size_t)mt * 32 + ks) * 2;
    g_Afrag[ib * 32 + t]       = make_uint4(hi[0], hi[1], hi[2], hi[3]);
    g_Afrag[(ib + 1) * 32 + t] = make_uint4(lo[0], lo[1], lo[2], lo[3]);
}

// ---- prep W ----------------------------------------------------------------
__global__ __launch_bounds__(256) void prep_W(const float* __restrict__ W) {
    int f = blockIdx.x * 256 + threadIdx.x;
    int t = f & 31, ngrp = (f >> 5) & 63, ks = f >> 11;
    uint32_t hi[8], lo[8];
#pragma unroll
    for (int nblk = 0; nblk < 4; nblk++)
#pragma unroll
        for (int reg = 0; reg < 2; reg++) {
            int k0 = ks * 16 + reg * 8 + (t & 3) * 2;
            int n  = ngrp * 32 + nblk * 8 + (t >> 2);
            float w0 = W[(size_t)k0 * FOURU + n];
            float w1 = W[(size_t)(k0 + 1) * FOURU + n];
            hi[nblk * 2 + reg] = pack_split_hi(w0, w1);
            lo[nblk * 2 + reg] = pack_split_lo(w0, w1);
        }
    size_t wb = (((size_t)ks * 2 + 0) * 64 + ngrp) * 32 + t;
    size_t wl = (((size_t)ks * 2 + 1) * 64 + ngrp) * 32 + t;
    g_Wfrag[wb * 2]     = make_uint4(hi[0], hi[1], hi[2], hi[3]);
    g_Wfrag[wb * 2 + 1] = make_uint4(hi[4], hi[5], hi[6], hi[7]);
    g_Wfrag[wl * 2]     = make_uint4(lo[0], lo[1], lo[2], lo[3]);
    g_Wfrag[wl * 2 + 1] = make_uint4(lo[4], lo[5], lo[6], lo[7]);
}

#define MMA16816(c, a, b0v, b1v)                                              \
    asm volatile(                                                             \
        "mma.sync.aligned.m16n8k16.row.col.f32.bf16.bf16.f32 "                \
        "{%0,%1,%2,%3}, {%4,%5,%6,%7}, {%8,%9}, {%0,%1,%2,%3};"               \
        : "+f"((c)[0]), "+f"((c)[1]), "+f"((c)[2]), "+f"((c)[3])              \
        : "r"((a).x), "r"((a).y), "r"((a).z), "r"((a).w),                     \
          "r"(b0v), "r"(b1v))

// ---- GEMM (unchanged) ------------------------------------------------------
__global__ __launch_bounds__(256) void gemm_mma(const float* __restrict__ bias) {
    const int tid = threadIdx.x;
    const int t = tid & 31, wid = tid >> 5;
    const int wm = wid & 1, wn = wid >> 1;
    const int mtb = blockIdx.y * 8 + wm * 4;
    const int ngrp = blockIdx.x * 4 + wn;

    float acc[4][4][4];
#pragma unroll
    for (int mi = 0; mi < 4; mi++)
#pragma unroll
        for (int ni = 0; ni < 4; ni++)
#pragma unroll
            for (int c = 0; c < 4; c++) acc[mi][ni][c] = 0.f;

#pragma unroll 2
    for (int ks = 0; ks < NKSTEP; ks++) {
        uint4 ah[4], al[4];
#pragma unroll
        for (int mi = 0; mi < 4; mi++) {
            size_t ib = ((size_t)(mtb + mi) * 32 + ks) * 2;
            ah[mi] = g_Afrag[ib * 32 + t];
            al[mi] = g_Afrag[(ib + 1) * 32 + t];
        }
        size_t wb = (((size_t)ks * 2 + 0) * 64 + ngrp) * 32 + t;
        size_t wl = (((size_t)ks * 2 + 1) * 64 + ngrp) * 32 + t;
        uint4 bh0 = g_Wfrag[wb * 2], bh1 = g_Wfrag[wb * 2 + 1];
        uint4 bl0 = g_Wfrag[wl * 2], bl1 = g_Wfrag[wl * 2 + 1];
        uint32_t bh[8] = {bh0.x, bh0.y, bh0.z, bh0.w, bh1.x, bh1.y, bh1.z, bh1.w};
        uint32_t bl[8] = {bl0.x, bl0.y, bl0.z, bl0.w, bl1.x, bl1.y, bl1.z, bl1.w};

#pragma unroll
        for (int mi = 0; mi < 4; mi++)
#pragma unroll
            for (int ni = 0; ni < 4; ni++) {
                MMA16816(acc[mi][ni], ah[mi], bh[ni * 2], bh[ni * 2 + 1]);
                MMA16816(acc[mi][ni], ah[mi], bl[ni * 2], bl[ni * 2 + 1]);
                MMA16816(acc[mi][ni], al[mi], bh[ni * 2], bh[ni * 2 + 1]);
            }
    }

    const int colbase = blockIdx.x * 128 + wn * 32 + (t & 3) * 2;
    const int rowbase = blockIdx.y * 128 + wm * 64 + (t >> 2);
    float2 bv[4];
#pragma unroll
    for (int ni = 0; ni < 4; ni++)
        bv[ni] = *(const float2*)(bias + colbase + ni * 8);
#pragma unroll
    for (int mi = 0; mi < 4; mi++) {
        int r0 = rowbase + mi * 16;
#pragma unroll
        for (int ni = 0; ni < 4; ni++) {
            int col = colbase + ni * 8;
            float2 o0 = make_float2(acc[mi][ni][0] + bv[ni].x,
                                    acc[mi][ni][1] + bv[ni].y);
            float2 o1 = make_float2(acc[mi][ni][2] + bv[ni].x,
                                    acc[mi][ni][3] + bv[ni].y);
            __stcs((float2*)(g_xz + (size_t)r0 * FOURU + col), o0);
            __stcs((float2*)(g_xz + (size_t)(r0 + 8) * FOURU + col), o1);
        }
    }
}

// ---- persistent LSTM recurrence: dataflow via padded per-producer flags ----
// CTA (ug,bg): units [16ug,+16), batches [16bg,+16). 256 threads.
// h(t) consumed in 4 chunks of 8 producer-blocks, double-buffered SMEM
// staging; warp0 polls the next chunk's flags. No group barrier.
__global__ __launch_bounds__(TPB, 1) void lstm_recur(const float* __restrict__ R)
{
    extern __shared__ float sm[];
    float* R4  = sm + SM_R4;
    float* h4  = sm + SM_H4;     // 2 x [32 kq][68]
    float* xzs = sm + SM_XZ;

    const int tid = threadIdx.x;
    const int ug = blockIdx.x >> 2, bg = blockIdx.x & 3;
    const int u0 = ug * 16, b0 = bg * 16;
    const int b_l = tid & 15, u_l = tid >> 4;

    // R4[kq][u][g*4+kl] = R[(kq*4+kl)][g*512+u0+u]
    for (int i = tid; i < 32768; i += TPB) {
        int kq = i >> 8, u = (i >> 4) & 15, e = i & 15, g = e >> 2, kl = e & 3;
        R4[i] = R[(size_t)(kq * 4 + kl) * FOURU + g * UNITS + u0 + u];
    }

    // xz staging: thread -> (pb, pg, pq)
    const int pb = tid >> 4, pg = (tid >> 2) & 3, pq = tid & 3;
    const float* xz_thread = g_xz + (size_t)(b0 + pb) * TSTEPS * FOURU
                             + pg * UNITS + u0 + pq * 4;
    {
        float4 v = __ldcs((const float4*)xz_thread);
        float vv[4] = {v.x, v.y, v.z, v.w};
#pragma unroll
        for (int j = 0; j < 4; j++)
            xzs[pg * 272 + (pq * 4 + j) * 17 + pb] = vv[j];
    }
    __syncthreads();

    unsigned* myflag = &g_flag[bg][ug][0];
    const int c0 = ((ug >> 3) + 1) & 3;      // start after own chunk
    const int srow = tid >> 4, scol = tid & 15;

    float c_state = 0.f;

    for (int t = 0; t < TSTEPS; t++) {
        const int par = t & 1;
        float4 xnext = make_float4(0.f, 0.f, 0.f, 0.f);
        if (t + 1 < TSTEPS)
            xnext = __ldcs((const float4*)(xz_thread + (size_t)(t + 1) * FOURU));

        int c = c0;
        if (tid < 32) {
            const unsigned* fp = &g_flag[bg][c * 8 + (tid & 7)][0];
            unsigned f;
            do { f = ld_acquire(fp); } while (__any_sync(0xffffffffu, f < (unsigned)t));
        }
        __syncthreads();

        float hreg[8];
#pragma unroll
        for (int r = 0; r < 8; r++)
            hreg[r] = __ldcg(&g_hT[par][c * 128 + r * 16 + srow][b0 + scol]);

        u64t a0 = 0ull, a1 = 0ull, a2 = 0ull, a3 = 0ull;

#pragma unroll
        for (int i = 0; i < 4; i++) {
            float* buf = h4 + (i & 1) * 2176;
#pragma unroll
            for (int r = 0; r < 8; r++) {
                int lk = r * 16 + srow;
                buf[(lk >> 2) * 68 + scol * 4 + (lk & 3)] = hreg[r];
            }
            int cn = (c + 1) & 3;
            if (i < 3 && tid < 32) {
                const unsigned* fp = &g_flag[bg][cn * 8 + (tid & 7)][0];
                unsigned f;
                do { f = ld_acquire(fp); } while (__any_sync(0xffffffffu, f < (unsigned)t));
            }
            __syncthreads();
            if (i < 3) {
#pragma unroll
                for (int r = 0; r < 8; r++)
                    hreg[r] = __ldcg(&g_hT[par][cn * 128 + r * 16 + srow][b0 + scol]);
            }
            const float* hrow = buf + b_l * 4;
            const float* rrow = R4 + u_l * 16 + c * 32 * 256;
#pragma unroll 8
            for (int lkq = 0; lkq < 32; lkq++) {
                ulonglong2 hh = *(const ulonglong2*)(hrow + lkq * 68);
                ulonglong2 r0 = *(const ulonglong2*)(rrow + lkq * 256);
                ulonglong2 r1 = *(const ulonglong2*)(rrow + lkq * 256 + 4);
                ulonglong2 r2 = *(const ulonglong2*)(rrow + lkq * 256 + 8);
                ulonglong2 r3 = *(const ulonglong2*)(rrow + lkq * 256 + 12);
                ffma2(a0, r0.x, hh.x); ffma2(a1, r1.x, hh.x);
                ffma2(a2, r2.x, hh.x); ffma2(a3, r3.x, hh.x);
                ffma2(a0, r0.y, hh.y); ffma2(a1, r1.y, hh.y);
                ffma2(a2, r2.y, hh.y); ffma2(a3, r3.y, hh.y);
            }
            c = cn;
        }

        const float* xb = xzs + par * 1088 + u_l * 17 + b_l;
        float2 p;
        p = unpack2(a0); float z1 = p.x + p.y + xb[0];
        p = unpack2(a1); float z2 = p.x + p.y + xb[272];
        p = unpack2(a2); float z3 = p.x + p.y + xb[544];
        p = unpack2(a3); float z4 = p.x + p.y + xb[816];

        float v1 = ftanh(z1);
        float v2 = fsig(z2);
        float v3 = fsig(z3);
        float v4 = fsig(z4);
        c_state = v1 * v2 + v3 * c_state;
        float hnew = v4 * ftanh(c_state);

        __stcg(&g_hT[(t + 1) & 1][u0 + u_l][b0 + b_l], hnew);
        __syncthreads();                      // all tile stores done
        if (tid == 0) st_release(myflag, (unsigned)(t + 1));

        if (t + 1 < TSTEPS) {
            float vv[4] = {xnext.x, xnext.y, xnext.z, xnext.w};
            float* dst = xzs + ((t + 1) & 1) * 1088;
#pragma unroll
            for (int j = 0; j < 4; j++)
                dst[pg * 272 + (pq * 4 + j) * 17 + pb] = vv[j];
        }
    }
}

// ---- final dense + softmax --------------------------------------------------
__global__ void fc_softmax(const float* __restrict__ fc_w,
                           const float* __restrict__ fc_b,
                           float* __restrict__ out)
{
    const int b = blockIdx.x;
    const int l = threadIdx.x;
    float a0 = 0.f, a1 = 0.f, a2 = 0.f, a3 = 0.f;
    for (int k = l * 16; k < l * 16 + 16; k++) {
        float h = g_hT[0][k][b];          // h(1024) parity 0
        float4 wv = *(const float4*)&fc_w[k * 4];
        a0 += h * wv.x; a1 += h * wv.y;
        a2 += h * wv.z; a3 += h * wv.w;
    }
#pragma unroll
    for (int o = 16; o > 0; o >>= 1) {
        a0 += __shfl_down_sync(0xffffffffu, a0, o);
        a1 += __shfl_down_sync(0xffffffffu, a1, o);
        a2 += __shfl_down_sync(0xffffffffu, a2, o);
        a3 += __shfl_down_sync(0xffffffffu, a3, o);
    }
    if (l == 0) {
        float z0 = a0 + fc_b[0], z1 = a1 + fc_b[1];
        float z2 = a2 + fc_b[2], z3 = a3 + fc_b[3];
        float m = fmaxf(fmaxf(z0, z1), fmaxf(z2, z3));
        float e0 = __expf(z0 - m), e1 = __expf(z1 - m);
        float e2 = __expf(z2 - m), e3 = __expf(z3 - m);
        float inv = __fdividef(1.f, e0 + e1 + e2 + e3);
        out[b * 4 + 0] = e0 * inv;
        out[b * 4 + 1] = e1 * inv;
        out[b * 4 + 2] = e2 * inv;
        out[b * 4 + 3] = e3 * inv;
    }
}

// ---------------------------------------------------------------------------
extern "C" void kernel_launch(void* const* d_in, const int* in_sizes, int n_in,
                              void* d_out, int out_size)
{
    const float* tx      = (const float*)d_in[0];
    const float* kernelW = (const float*)d_in[1];
    const float* R       = (const float*)d_in[2];
    const float* bias    = (const float*)d_in[3];
    const float* fc_w    = (const float*)d_in[4];
    const float* fc_b    = (const float*)d_in[5];
    float* out           = (float*)d_out;

    cudaFuncSetAttribute(lstm_recur,
                         cudaFuncAttributeMaxDynamicSharedMemorySize, SM_BYTES);

    init_kernel<<<(2 * UNITS * BATCH + 255) / 256, 256>>>();
    prep_A<<<16384, 256>>>(tx);
    prep_W<<<256, 256>>>(kernelW);
    gemm_mma<<<dim3(16, 512), 256>>>(bias);
    lstm_recur<<<NCTA, TPB, SM_BYTES>>>(R);
    fc_softmax<<<BATCH, 32>>>(fc_w, fc_b, out);
    (void)in_sizes; (void)n_in; (void)out_size;
}

// round 11
// speedup vs baseline: 2.0474x; 2.0474x over previous
#include <cuda_runtime.h>
#include <cuda_bf16.h>
#include <cstdint>

// LSTM  B=64, T=1024, D=512, U=512, OUT=4
#define BATCH    64
#define TSTEPS   1024
#define DIN      512
#define UNITS    512
#define FOURU    2048
#define NCTA     128
#define TPB      256
#define NBG      4
#define GROUP_CTAS 32
#define NMTILE   4096
#define NKSTEP   32

// recurrence smem offsets (bytes)
#define SM_BHI   0            // bf16 [64 n][520]  : 66560
#define SM_BLO   66560        // bf16 [64 n][520]  : 66560
#define SM_AHI   133120       // bf16 [16 b][520]  : 16640
#define SM_ALO   149760       // bf16 [16 b][520]  : 16640
#define SM_Z     166400       // f32  [16 b][68]   : 4352
#define SM_RED   170752       // f32  [4][32][8]   : 4096
#define SM_HT    174848       // f32  [16 j][17]   : 1088
#define SM_XZ    175936       // f32  [2][1088]    : 8704
#define SM_BYTES 184640

__device__ float    g_xz[(size_t)BATCH * TSTEPS * FOURU];
__device__ uint4    g_Afrag[(size_t)NMTILE * NKSTEP * 2 * 32];
__device__ uint4    g_Wfrag[(size_t)NKSTEP * 2 * 64 * 32 * 2];
__device__ float    g_h[2][BATCH][UNITS];        // batch-major
__device__ unsigned g_arrive[NBG * 32];
__device__ unsigned g_gen[NBG * 32];

__device__ __forceinline__ float fsig(float x) {
    return __fdividef(1.f, 1.f + __expf(-x));
}
__device__ __forceinline__ float ftanh(float x) {
    return 1.f - __fdividef(2.f, __expf(2.f * x) + 1.f);
}
__device__ __forceinline__ unsigned atom_add_acqrel(unsigned* p, unsigned v) {
    unsigned old;
    asm volatile("atom.acq_rel.gpu.global.add.u32 %0, [%1], %2;"
                 : "=r"(old) : "l"(p), "r"(v) : "memory");
    return old;
}
__device__ __forceinline__ void st_release(unsigned* p, unsigned v) {
    asm volatile("st.release.gpu.global.u32 [%0], %1;" :: "l"(p), "r"(v) : "memory");
}
__device__ __forceinline__ unsigned ld_acquire(const unsigned* p) {
    unsigned v;
    asm volatile("ld.acquire.gpu.global.u32 %0, [%1];" : "=r"(v) : "l"(p) : "memory");
    return v;
}
__device__ __forceinline__ uint32_t pack_split_hi(float a, float b) {
    __nv_bfloat16 ha = __float2bfloat16(a), hb = __float2bfloat16(b);
    return (uint32_t)*(uint16_t*)&ha | ((uint32_t)*(uint16_t*)&hb << 16);
}
__device__ __forceinline__ uint32_t pack_split_lo(float a, float b) {
    __nv_bfloat16 ha = __float2bfloat16(a), hb = __float2bfloat16(b);
    __nv_bfloat16 la = __float2bfloat16(a - __bfloat162float(ha));
    __nv_bfloat16 lb = __float2bfloat16(b - __bfloat162float(hb));
    return (uint32_t)*(uint16_t*)&la | ((uint32_t)*(uint16_t*)&lb << 16);
}
__device__ __forceinline__ uint32_t smem_u32(const void* p) {
    return (uint32_t)__cvta_generic_to_shared(p);
}

__global__ void init_kernel() {
    int i = blockIdx.x * blockDim.x + threadIdx.x;
    if (i < 2 * BATCH * UNITS) ((float*)g_h)[i] = 0.f;
    if (i < NBG * 32) { g_arrive[i] = 0u; g_gen[i] = 0u; }
}

// ---- prep A (xz GEMM operand, unchanged) ----------------------------------
__global__ __launch_bounds__(256) void prep_A(const float* __restrict__ A) {
    int f = blockIdx.x * 256 + threadIdx.x;
    int t = f & 31, ks = (f >> 5) & 31, mt = f >> 10;
    uint32_t hi[4], lo[4];
#pragma unroll
    for (int r = 0; r < 4; r++) {
        int m  = mt * 16 + (r & 1) * 8 + (t >> 2);
        int k0 = ks * 16 + ((r & 2) << 2) + ((t & 3) << 1);
        float2 av = *(const float2*)(A + (size_t)m * DIN + k0);
        hi[r] = pack_split_hi(av.x, av.y);
        lo[r] = pack_split_lo(av.x, av.y);
    }
    size_t ib = ((size_t)mt * 32 + ks) * 2;
    g_Afrag[ib * 32 + t]       = make_uint4(hi[0], hi[1], hi[2], hi[3]);
    g_Afrag[(ib + 1) * 32 + t] = make_uint4(lo[0], lo[1], lo[2], lo[3]);
}

// ---- prep W (unchanged) ----------------------------------------------------
__global__ __launch_bounds__(256) void prep_W(const float* __restrict__ W) {
    int f = blockIdx.x * 256 + threadIdx.x;
    int t = f & 31, ngrp = (f >> 5) & 63, ks = f >> 11;
    uint32_t hi[8], lo[8];
#pragma unroll
    for (int nblk = 0; nblk < 4; nblk++)
#pragma unroll
        for (int reg = 0; reg < 2; reg++) {
            int k0 = ks * 16 + reg * 8 + (t & 3) * 2;
            int n  = ngrp * 32 + nblk * 8 + (t >> 2);
            float w0 = W[(size_t)k0 * FOURU + n];
            float w1 = W[(size_t)(k0 + 1) * FOURU + n];
            hi[nblk * 2 + reg] = pack_split_hi(w0, w1);
            lo[nblk * 2 + reg] = pack_split_lo(w0, w1);
        }
    size_t wb = (((size_t)ks * 2 + 0) * 64 + ngrp) * 32 + t;
    size_t wl = (((size_t)ks * 2 + 1) * 64 + ngrp) * 32 + t;
    g_Wfrag[wb * 2]     = make_uint4(hi[0], hi[1], hi[2], hi[3]);
    g_Wfrag[wb * 2 + 1] = make_uint4(hi[4], hi[5], hi[6], hi[7]);
    g_Wfrag[wl * 2]     = make_uint4(lo[0], lo[1], lo[2], lo[3]);
    g_Wfrag[wl * 2 + 1] = make_uint4(lo[4], lo[5], lo[6], lo[7]);
}

#define MMA16816(c, a, b0v, b1v)                                              \
    asm volatile(                                                             \
        "mma.sync.aligned.m16n8k16.row.col.f32.bf16.bf16.f32 "                \
        "{%0,%1,%2,%3}, {%4,%5,%6,%7}, {%8,%9}, {%0,%1,%2,%3};"               \
        : "+f"((c)[0]), "+f"((c)[1]), "+f"((c)[2]), "+f"((c)[3])              \
        : "r"((a).x), "r"((a).y), "r"((a).z), "r"((a).w),                     \
          "r"(b0v), "r"(b1v))

#define LDSM4(r, addr)                                                        \
    asm volatile("ldmatrix.sync.aligned.m8n8.x4.shared.b16 "                  \
                 "{%0,%1,%2,%3}, [%4];"                                       \
                 : "=r"((r).x), "=r"((r).y), "=r"((r).z), "=r"((r).w)         \
                 : "r"(addr))

// ---- xz GEMM (unchanged) ---------------------------------------------------
__global__ __launch_bounds__(256) void gemm_mma(const float* __restrict__ bias) {
    const int tid = threadIdx.x;
    const int t = tid & 31, wid = tid >> 5;
    const int wm = wid & 1, wn = wid >> 1;
    const int mtb = blockIdx.y * 8 + wm * 4;
    const int ngrp = blockIdx.x * 4 + wn;

    float acc[4][4][4];
#pragma unroll
    for (int mi = 0; mi < 4; mi++)
#pragma unroll
        for (int ni = 0; ni < 4; ni++)
#pragma unroll
            for (int c = 0; c < 4; c++) acc[mi][ni][c] = 0.f;

#pragma unroll 2
    for (int ks = 0; ks < NKSTEP; ks++) {
        uint4 ah[4], al[4];
#pragma unroll
        for (int mi = 0; mi < 4; mi++) {
            size_t ib = ((size_t)(mtb + mi) * 32 + ks) * 2;
            ah[mi] = g_Afrag[ib * 32 + t];
            al[mi] = g_Afrag[(ib + 1) * 32 + t];
        }
        size_t wb = (((size_t)ks * 2 + 0) * 64 + ngrp) * 32 + t;
        size_t wl = (((size_t)ks * 2 + 1) * 64 + ngrp) * 32 + t;
        uint4 bh0 = g_Wfrag[wb * 2], bh1 = g_Wfrag[wb * 2 + 1];
        uint4 bl0 = g_Wfrag[wl * 2], bl1 = g_Wfrag[wl * 2 + 1];
        uint32_t bh[8] = {bh0.x, bh0.y, bh0.z, bh0.w, bh1.x, bh1.y, bh1.z, bh1.w};
        uint32_t bl[8] = {bl0.x, bl0.y, bl0.z, bl0.w, bl1.x, bl1.y, bl1.z, bl1.w};

#pragma unroll
        for (int mi = 0; mi < 4; mi++)
#pragma unroll
            for (int ni = 0; ni < 4; ni++) {
                MMA16816(acc[mi][ni], ah[mi], bh[ni * 2], bh[ni * 2 + 1]);
                MMA16816(acc[mi][ni], ah[mi], bl[ni * 2], bl[ni * 2 + 1]);
                MMA16816(acc[mi][ni], al[mi], bh[ni * 2], bh[ni * 2 + 1]);
            }
    }

    const int colbase = blockIdx.x * 128 + wn * 32 + (t & 3) * 2;
    const int rowbase = blockIdx.y * 128 + wm * 64 + (t >> 2);
    float2 bv[4];
#pragma unroll
    for (int ni = 0; ni < 4; ni++)
        bv[ni] = *(const float2*)(bias + colbase + ni * 8);
#pragma unroll
    for (int mi = 0; mi < 4; mi++) {
        int r0 = rowbase + mi * 16;
#pragma unroll
        for (int ni = 0; ni < 4; ni++) {
            int col = colbase + ni * 8;
            float2 o0 = make_float2(acc[mi][ni][0] + bv[ni].x,
                                    acc[mi][ni][1] + bv[ni].y);
            float2 o1 = make_float2(acc[mi][ni][2] + bv[ni].x,
                                    acc[mi][ni][3] + bv[ni].y);
            __stcs((float2*)(g_xz + (size_t)r0 * FOURU + col), o0);
            __stcs((float2*)(g_xz + (size_t)(r0 + 8) * FOURU + col), o1);
        }
    }
}

// ---- persistent LSTM recurrence: tensor-core z = h @ R ---------------------
// CTA (ug,bg): units [16ug,+16), batches [16bg,+16). z = m16 x n64 x k512.
// R split-bf16 resident in SMEM (B operand); h staged per step (A operand).
// 8 warps = 4 n-pairs x 2 k-halves; SMEM k-reduce; R8 barrier.
__global__ __launch_bounds__(TPB, 1) void lstm_recur(const float* __restrict__ R)
{
    extern __shared__ char smc[];
    __nv_bfloat16* Bhi = (__nv_bfloat16*)(smc + SM_BHI);
    __nv_bfloat16* Blo = (__nv_bfloat16*)(smc + SM_BLO);
    uint32_t* AhiW = (uint32_t*)(smc + SM_AHI);
    uint32_t* AloW = (uint32_t*)(smc + SM_ALO);
    float* zbuf = (float*)(smc + SM_Z);
    float* red  = (float*)(smc + SM_RED);
    float* ht   = (float*)(smc + SM_HT);
    float* xzs  = (float*)(smc + SM_XZ);

    const int tid = threadIdx.x;
    const int wid = tid >> 5, lane = tid & 31;
    const int ug = blockIdx.x >> 2, bg = blockIdx.x & 3;
    const int u0 = ug * 16, b0 = bg * 16;

    // ---- build B (R slice) once: B[n][k] = R[k][g*512+u0+j], n = g*16+j ----
    for (int i = tid; i < 64 * 512; i += TPB) {
        int k = i & 511, n = i >> 9;
        int g = n >> 4, j = n & 15;
        float v = R[(size_t)k * FOURU + g * UNITS + u0 + j];
        __nv_bfloat16 hb = __float2bfloat16(v);
        __nv_bfloat16 lb = __float2bfloat16(v - __bfloat162float(hb));
        Bhi[n * 520 + k] = hb;
        Blo[n * 520 + k] = lb;
    }

    // ---- xz staging map (as before): thread -> (pb, pg, pq) ----------------
    const int pb = tid >> 4, pg = (tid >> 2) & 3, pq = tid & 3;
    const float* xz_thread = g_xz + (size_t)(b0 + pb) * TSTEPS * FOURU
                             + pg * UNITS + u0 + pq * 4;
    {
        float4 v = __ldcs((const float4*)xz_thread);
        float vv[4] = {v.x, v.y, v.z, v.w};
#pragma unroll
        for (int j = 0; j < 4; j++)
            xzs[pg * 272 + (pq * 4 + j) * 17 + pb] = vv[j];
    }
    __syncthreads();

    // ---- lane-invariant LDSM addresses -------------------------------------
    const int khalf = wid >> 2, npair = wid & 3;
    const int aRow = (lane & 7) + ((lane >> 3) & 1) * 8;
    const int aKof = ((lane >> 4) & 1) * 16;            // bytes
    const uint32_t aHiAddr = smem_u32(smc + SM_AHI) + aRow * 1040 + aKof;
    const uint32_t aLoAddr = smem_u32(smc + SM_ALO) + aRow * 1040 + aKof;
    const int bRow = npair * 16 + ((lane >> 4) & 1) * 8 + (lane & 7);
    const int bKof = ((lane >> 3) & 1) * 16;
    const uint32_t bHiAddr = smem_u32(smc + SM_BHI) + bRow * 1040 + bKof;
    const uint32_t bLoAddr = smem_u32(smc + SM_BLO) + bRow * 1040 + bKof;

    // A-staging map: b = tid>>4, 8 chunks of 4 floats at u = (tid&15)*4+q*64
    const int sb = tid >> 4, su = (tid & 15) * 4;
    // gates map
    const int b_l = tid & 15, j_l = tid >> 4;

    unsigned* arrive = &g_arrive[bg * 32];
    unsigned* gen    = &g_gen[bg * 32];

    float c_state = 0.f;

    for (int t = 0; t < TSTEPS; t++) {
        const int par = t & 1;
        float4 xnext = make_float4(0.f, 0.f, 0.f, 0.f);
        if (t + 1 < TSTEPS)
            xnext = __ldcs((const float4*)(xz_thread + (size_t)(t + 1) * FOURU));

        // ---- stage A = h(t)[16 b][512 k] as split bf16 ----
        const float* hsrc = &g_h[par][b0 + sb][0];
#pragma unroll
        for (int q = 0; q < 8; q++) {
            int u = su + q * 64;
            float4 v = __ldcg((const float4*)(hsrc + u));
            uint32_t h01, h23, l01, l23;
            asm("cvt.rn.bf16x2.f32 %0, %1, %2;" : "=r"(h01) : "f"(v.y), "f"(v.x));
            asm("cvt.rn.bf16x2.f32 %0, %1, %2;" : "=r"(h23) : "f"(v.w), "f"(v.z));
            float f0 = __uint_as_float(h01 << 16);
            float f1 = __uint_as_float(h01 & 0xffff0000u);
            float f2 = __uint_as_float(h23 << 16);
            float f3 = __uint_as_float(h23 & 0xffff0000u);
            asm("cvt.rn.bf16x2.f32 %0, %1, %2;"
                : "=r"(l01) : "f"(v.y - f1), "f"(v.x - f0));
            asm("cvt.rn.bf16x2.f32 %0, %1, %2;"
                : "=r"(l23) : "f"(v.w - f3), "f"(v.z - f2));
            int w = sb * 260 + u / 2;
            AhiW[w] = h01; AhiW[w + 1] = h23;
            AloW[w] = l01; AloW[w + 1] = l23;
        }
        __syncthreads();

        // ---- MMA: this warp: n-tiles {2*npair, 2*npair+1}, k-half khalf ----
        float acc0[4] = {0.f, 0.f, 0.f, 0.f};
        float acc1[4] = {0.f, 0.f, 0.f, 0.f};
#pragma unroll
        for (int kt = khalf * 16; kt < khalf * 16 + 16; kt++) {
            uint32_t ofs = kt * 32;
            uint4 ah, al, bh, bl;
            LDSM4(ah, aHiAddr + ofs);
            LDSM4(al, aLoAddr + ofs);
            LDSM4(bh, bHiAddr + ofs);
            LDSM4(bl, bLoAddr + ofs);
            MMA16816(acc0, ah, bh.x, bh.y);
            MMA16816(acc1, ah, bh.z, bh.w);
            MMA16816(acc0, ah, bl.x, bl.y);
            MMA16816(acc1, ah, bl.z, bl.w);
            MMA16816(acc0, al, bh.x, bh.y);
            MMA16816(acc1, al, bh.z, bh.w);
        }

        // ---- k-half reduce via SMEM ----
        if (khalf == 1) {
            float* rb = red + (npair * 32 + lane) * 8;
            *(float4*)rb       = make_float4(acc0[0], acc0[1], acc0[2], acc0[3]);
            *(float4*)(rb + 4) = make_float4(acc1[0], acc1[1], acc1[2], acc1[3]);
        }
        __syncthreads();
        if (khalf == 0) {
            const float* rb = red + (npair * 32 + lane) * 8;
            float4 p0 = *(const float4*)rb;
            float4 p1 = *(const float4*)(rb + 4);
            acc0[0] += p0.x; acc0[1] += p0.y; acc0[2] += p0.z; acc0[3] += p0.w;
            acc1[0] += p1.x; acc1[1] += p1.y; acc1[2] += p1.z; acc1[3] += p1.w;
            // write z[b][n]: rows lane>>2 (+8), cols npair*16 + {0,8} + 2*(lane&3)
            int ra = lane >> 2, cb = (lane & 3) * 2;
            int n0 = npair * 16 + cb, n1 = npair * 16 + 8 + cb;
            *(float2*)&zbuf[ra * 68 + n0]       = make_float2(acc0[0], acc0[1]);
            *(float2*)&zbuf[(ra + 8) * 68 + n0] = make_float2(acc0[2], acc0[3]);
            *(float2*)&zbuf[ra * 68 + n1]       = make_float2(acc1[0], acc1[1]);
            *(float2*)&zbuf[(ra + 8) * 68 + n1] = make_float2(acc1[2], acc1[3]);
        }
        __syncthreads();

        // ---- gates: thread (b_l, j_l) ----
        {
            const float* zr = zbuf + b_l * 68 + j_l;
            const float* xb = xzs + par * 1088 + j_l * 17 + b_l;
            float z1 = zr[0]  + xb[0];
            float z2 = zr[16] + xb[272];
            float z3 = zr[32] + xb[544];
            float z4 = zr[48] + xb[816];
            float v1 = ftanh(z1);
            float v2 = fsig(z2);
            float v3 = fsig(z3);
            float v4 = fsig(z4);
            c_state = v1 * v2 + v3 * c_state;
            float hnew = v4 * ftanh(c_state);
            ht[j_l * 17 + b_l] = hnew;
        }
        __syncthreads();

        // ---- coalesced h(t+1) writeback: u fast-varying ----
        {
            float hv = ht[(tid & 15) * 17 + (tid >> 4)];
            __stcg(&g_h[par ^ 1][b0 + (tid >> 4)][u0 + (tid & 15)], hv);
        }
        __syncthreads();

        // ---- R8 barrier: arrive early, stage xz, poll ----
        if (tid == 0) {
            unsigned prev = atom_add_acqrel(arrive, 1u);
            if ((prev & 31u) == 31u)
                st_release(gen, (unsigned)(t + 1));
        }
        if (t + 1 < TSTEPS) {
            float vv[4] = {xnext.x, xnext.y, xnext.z, xnext.w};
            float* dst = xzs + ((t + 1) & 1) * 1088;
#pragma unroll
            for (int j = 0; j < 4; j++)
                dst[pg * 272 + (pq * 4 + j) * 17 + pb] = vv[j];
        }
        if (tid == 0) {
            while (ld_acquire(gen) < (unsigned)(t + 1)) { }
        }
        __syncthreads();
    }
}

// ---- final dense + softmax --------------------------------------------------
__global__ void fc_softmax(const float* __restrict__ fc_w,
                           const float* __restrict__ fc_b,
                           float* __restrict__ out)
{
    const int b = blockIdx.x;
    const int l = threadIdx.x;
    float a0 = 0.f, a1 = 0.f, a2 = 0.f, a3 = 0.f;
    const float* hg = &g_h[0][b][0];   // t=1023 wrote parity 0
    for (int k = l * 16; k < l * 16 + 16; k += 4) {
        float4 hv = *(const float4*)(hg + k);
        float hx[4] = {hv.x, hv.y, hv.z, hv.w};
#pragma unroll
        for (int q = 0; q < 4; q++) {
            float4 wv = *(const float4*)&fc_w[(k + q) * 4];
            a0 += hx[q] * wv.x; a1 += hx[q] * wv.y;
            a2 += hx[q] * wv.z; a3 += hx[q] * wv.w;
        }
    }
#pragma unroll
    for (int o = 16; o > 0; o >>= 1) {
        a0 += __shfl_down_sync(0xffffffffu, a0, o);
        a1 += __shfl_down_sync(0xffffffffu, a1, o);
        a2 += __shfl_down_sync(0xffffffffu, a2, o);
        a3 += __shfl_down_sync(0xffffffffu, a3, o);
    }
    if (l == 0) {
        float z0 = a0 + fc_b[0], z1 = a1 + fc_b[1];
        float z2 = a2 + fc_b[2], z3 = a3 + fc_b[3];
        float m = fmaxf(fmaxf(z0, z1), fmaxf(z2, z3));
        float e0 = __expf(z0 - m), e1 = __expf(z1 - m);
        float e2 = __expf(z2 - m), e3 = __expf(z3 - m);
        float inv = __fdividef(1.f, e0 + e1 + e2 + e3);
        out[b * 4 + 0] = e0 * inv;
        out[b * 4 + 1] = e1 * inv;
        out[b * 4 + 2] = e2 * inv;
        out[b * 4 + 3] = e3 * inv;
    }
}

// ---------------------------------------------------------------------------
extern "C" void kernel_launch(void* const* d_in, const int* in_sizes, int n_in,
                              void* d_out, int out_size)
{
    const float* tx      = (const float*)d_in[0];
    const float* kernelW = (const float*)d_in[1];
    const float* R       = (const float*)d_in[2];
    const float* bias    = (const float*)d_in[3];
    const float* fc_w    = (const float*)d_in[4];
    const float* fc_b    = (const float*)d_in[5];
    float* out           = (float*)d_out;

    cudaFuncSetAttribute(lstm_recur,
                         cudaFuncAttributeMaxDynamicSharedMemorySize, SM_BYTES);

    init_kernel<<<(2 * BATCH * UNITS + 255) / 256, 256>>>();
    prep_A<<<16384, 256>>>(tx);
    prep_W<<<256, 256>>>(kernelW);
    gemm_mma<<<dim3(16, 512), 256>>>(bias);
    lstm_recur<<<NCTA, TPB, SM_BYTES>>>(R);
    fc_softmax<<<BATCH, 32>>>(fc_w, fc_b, out);
    (void)in_sizes; (void)n_in; (void)out_size;
}

// round 12
// speedup vs baseline: 2.1962x; 1.0727x over previous
#include <cuda_runtime.h>
#include <cuda_bf16.h>
#include <cstdint>

// LSTM  B=64, T=1024, D=512, U=512, OUT=4
#define BATCH    64
#define TSTEPS   1024
#define DIN      512
#define UNITS    512
#define FOURU    2048
#define NCTA     128
#define TPB      256
#define NBG      4
#define GROUP_CTAS 32
#define NMTILE   4096
#define NKSTEP   32

// recurrence smem offsets (bytes)
#define SM_BHI   0            // bf16 [64 n][520]     : 66560
#define SM_BLO   66560        // bf16 [64 n][520]     : 66560
#define SM_AHI   133120       // bf16 [16 b][520]     : 16640
#define SM_ALO   149760       // bf16 [16 b][520]     : 16640
#define SM_Z     166400       // f32  [2][16 b][68]   : 8704
#define SM_XZ    175104       // f32  [2][1088]       : 8704
#define SM_BYTES 183808

__device__ float    g_xz[(size_t)BATCH * TSTEPS * FOURU];
__device__ uint4    g_Afrag[(size_t)NMTILE * NKSTEP * 2 * 32];
__device__ uint4    g_Wfrag[(size_t)NKSTEP * 2 * 64 * 32 * 2];
__device__ float    g_h[2][BATCH][UNITS];        // batch-major
__device__ unsigned g_arrive[NBG * 32];
__device__ unsigned g_gen[NBG * 32];

__device__ __forceinline__ float fsig(float x) {
    return __fdividef(1.f, 1.f + __expf(-x));
}
__device__ __forceinline__ float ftanh(float x) {
    return 1.f - __fdividef(2.f, __expf(2.f * x) + 1.f);
}
__device__ __forceinline__ unsigned atom_add_acqrel(unsigned* p, unsigned v) {
    unsigned old;
    asm volatile("atom.acq_rel.gpu.global.add.u32 %0, [%1], %2;"
                 : "=r"(old) : "l"(p), "r"(v) : "memory");
    return old;
}
__device__ __forceinline__ void st_release(unsigned* p, unsigned v) {
    asm volatile("st.release.gpu.global.u32 [%0], %1;" :: "l"(p), "r"(v) : "memory");
}
__device__ __forceinline__ unsigned ld_acquire(const unsigned* p) {
    unsigned v;
    asm volatile("ld.acquire.gpu.global.u32 %0, [%1];" : "=r"(v) : "l"(p) : "memory");
    return v;
}
__device__ __forceinline__ uint32_t pack_split_hi(float a, float b) {
    __nv_bfloat16 ha = __float2bfloat16(a), hb = __float2bfloat16(b);
    return (uint32_t)*(uint16_t*)&ha | ((uint32_t)*(uint16_t*)&hb << 16);
}
__device__ __forceinline__ uint32_t pack_split_lo(float a, float b) {
    __nv_bfloat16 ha = __float2bfloat16(a), hb = __float2bfloat16(b);
    __nv_bfloat16 la = __float2bfloat16(a - __bfloat162float(ha));
    __nv_bfloat16 lb = __float2bfloat16(b - __bfloat162float(hb));
    return (uint32_t)*(uint16_t*)&la | ((uint32_t)*(uint16_t*)&lb << 16);
}
__device__ __forceinline__ uint32_t smem_u32(const void* p) {
    return (uint32_t)__cvta_generic_to_shared(p);
}

__global__ void init_kernel() {
    int i = blockIdx.x * blockDim.x + threadIdx.x;
    if (i < 2 * BATCH * UNITS) ((float*)g_h)[i] = 0.f;
    if (i < NBG * 32) { g_arrive[i] = 0u; g_gen[i] = 0u; }
}

// ---- prep A (unchanged) ----------------------------------------------------
__global__ __launch_bounds__(256) void prep_A(const float* __restrict__ A) {
    int f = blockIdx.x * 256 + threadIdx.x;
    int t = f & 31, ks = (f >> 5) & 31, mt = f >> 10;
    uint32_t hi[4], lo[4];
#pragma unroll
    for (int r = 0; r < 4; r++) {
        int m  = mt * 16 + (r & 1) * 8 + (t >> 2);
        int k0 = ks * 16 + ((r & 2) << 2) + ((t & 3) << 1);
        float2 av = *(const float2*)(A + (size_t)m * DIN + k0);
        hi[r] = pack_split_hi(av.x, av.y);
        lo[r] = pack_split_lo(av.x, av.y);
    }
    size_t ib = ((size_t)mt * 32 + ks) * 2;
    g_Afrag[ib * 32 + t]       = make_uint4(hi[0], hi[1], hi[2], hi[3]);
    g_Afrag[(ib + 1) * 32 + t] = make_uint4(lo[0], lo[1], lo[2], lo[3]);
}

// ---- prep W (unchanged) ----------------------------------------------------
__global__ __launch_bounds__(256) void prep_W(const float* __restrict__ W) {
    int f = blockIdx.x * 256 + threadIdx.x;
    int t = f & 31, ngrp = (f >> 5) & 63, ks = f >> 11;
    uint32_t hi[8], lo[8];
#pragma unroll
    for (int nblk = 0; nblk < 4; nblk++)
#pragma unroll
        for (int reg = 0; reg < 2; reg++) {
            int k0 = ks * 16 + reg * 8 + (t & 3) * 2;
            int n  = ngrp * 32 + nblk * 8 + (t >> 2);
            float w0 = W[(size_t)k0 * FOURU + n];
            float w1 = W[(size_t)(k0 + 1) * FOURU + n];
            hi[nblk * 2 + reg] = pack_split_hi(w0, w1);
            lo[nblk * 2 + reg] = pack_split_lo(w0, w1);
        }
    size_t wb = (((size_t)ks * 2 + 0) * 64 + ngrp) * 32 + t;
    size_t wl = (((size_t)ks * 2 + 1) * 64 + ngrp) * 32 + t;
    g_Wfrag[wb * 2]     = make_uint4(hi[0], hi[1], hi[2], hi[3]);
    g_Wfrag[wb * 2 + 1] = make_uint4(hi[4], hi[5], hi[6], hi[7]);
    g_Wfrag[wl * 2]     = make_uint4(lo[0], lo[1], lo[2], lo[3]);
    g_Wfrag[wl * 2 + 1] = make_uint4(lo[4], lo[5], lo[6], lo[7]);
}

#define MMA16816(c, a, b0v, b1v)                                              \
    asm volatile(                                                             \
        "mma.sync.aligned.m16n8k16.row.col.f32.bf16.bf16.f32 "                \
        "{%0,%1,%2,%3}, {%4,%5,%6,%7}, {%8,%9}, {%0,%1,%2,%3};"               \
        : "+f"((c)[0]), "+f"((c)[1]), "+f"((c)[2]), "+f"((c)[3])              \
        : "r"((a).x), "r"((a).y), "r"((a).z), "r"((a).w),                     \
          "r"(b0v), "r"(b1v))

#define LDSM4(r, addr)                                                        \
    asm volatile("ldmatrix.sync.aligned.m8n8.x4.shared.b16 "                  \
                 "{%0,%1,%2,%3}, [%4];"                                       \
                 : "=r"((r).x), "=r"((r).y), "=r"((r).z), "=r"((r).w)         \
                 : "r"(addr))

// ---- xz GEMM (unchanged) ---------------------------------------------------
__global__ __launch_bounds__(256) void gemm_mma(const float* __restrict__ bias) {
    const int tid = threadIdx.x;
    const int t = tid & 31, wid = tid >> 5;
    const int wm = wid & 1, wn = wid >> 1;
    const int mtb = blockIdx.y * 8 + wm * 4;
    const int ngrp = blockIdx.x * 4 + wn;

    float acc[4][4][4];
#pragma unroll
    for (int mi = 0; mi < 4; mi++)
#pragma unroll
        for (int ni = 0; ni < 4; ni++)
#pragma unroll
            for (int c = 0; c < 4; c++) acc[mi][ni][c] = 0.f;

#pragma unroll 2
    for (int ks = 0; ks < NKSTEP; ks++) {
        uint4 ah[4], al[4];
#pragma unroll
        for (int mi = 0; mi < 4; mi++) {
            size_t ib = ((size_t)(mtb + mi) * 32 + ks) * 2;
            ah[mi] = g_Afrag[ib * 32 + t];
            al[mi] = g_Afrag[(ib + 1) * 32 + t];
        }
        size_t wb = (((size_t)ks * 2 + 0) * 64 + ngrp) * 32 + t;
        size_t wl = (((size_t)ks * 2 + 1) * 64 + ngrp) * 32 + t;
        uint4 bh0 = g_Wfrag[wb * 2], bh1 = g_Wfrag[wb * 2 + 1];
        uint4 bl0 = g_Wfrag[wl * 2], bl1 = g_Wfrag[wl * 2 + 1];
        uint32_t bh[8] = {bh0.x, bh0.y, bh0.z, bh0.w, bh1.x, bh1.y, bh1.z, bh1.w};
        uint32_t bl[8] = {bl0.x, bl0.y, bl0.z, bl0.w, bl1.x, bl1.y, bl1.z, bl1.w};

#pragma unroll
        for (int mi = 0; mi < 4; mi++)
#pragma unroll
            for (int ni = 0; ni < 4; ni++) {
                MMA16816(acc[mi][ni], ah[mi], bh[ni * 2], bh[ni * 2 + 1]);
                MMA16816(acc[mi][ni], ah[mi], bl[ni * 2], bl[ni * 2 + 1]);
                MMA16816(acc[mi][ni], al[mi], bh[ni * 2], bh[ni * 2 + 1]);
            }
    }

    const int colbase = blockIdx.x * 128 + wn * 32 + (t & 3) * 2;
    const int rowbase = blockIdx.y * 128 + wm * 64 + (t >> 2);
    float2 bv[4];
#pragma unroll
    for (int ni = 0; ni < 4; ni++)
        bv[ni] = *(const float2*)(bias + colbase + ni * 8);
#pragma unroll
    for (int mi = 0; mi < 4; mi++) {
        int r0 = rowbase + mi * 16;
#pragma unroll
        for (int ni = 0; ni < 4; ni++) {
            int col = colbase + ni * 8;
            float2 o0 = make_float2(acc[mi][ni][0] + bv[ni].x,
                                    acc[mi][ni][1] + bv[ni].y);
            float2 o1 = make_float2(acc[mi][ni][2] + bv[ni].x,
                                    acc[mi][ni][3] + bv[ni].y);
            __stcs((float2*)(g_xz + (size_t)r0 * FOURU + col), o0);
            __stcs((float2*)(g_xz + (size_t)(r0 + 8) * FOURU + col), o1);
        }
    }
}

// ---- persistent LSTM recurrence: tensor-core z = h @ R ---------------------
// R11 structure with: dual-z buffers (no reduce round-trip), direct-coalesced
// gates mapping (no ht transpose), B-hi fragments register-resident.
__global__ __launch_bounds__(TPB, 1) void lstm_recur(const float* __restrict__ R)
{
    extern __shared__ char smc[];
    __nv_bfloat16* Bhi = (__nv_bfloat16*)(smc + SM_BHI);
    __nv_bfloat16* Blo = (__nv_bfloat16*)(smc + SM_BLO);
    uint32_t* AhiW = (uint32_t*)(smc + SM_AHI);
    uint32_t* AloW = (uint32_t*)(smc + SM_ALO);
    float* zbuf = (float*)(smc + SM_Z);       // [2][16][68]
    float* xzs  = (float*)(smc + SM_XZ);

    const int tid = threadIdx.x;
    const int wid = tid >> 5, lane = tid & 31;
    const int ug = blockIdx.x >> 2, bg = blockIdx.x & 3;
    const int u0 = ug * 16, b0 = bg * 16;

    // ---- build B (R slice) once: B[n][k] = R[k][g*512+u0+j], n = g*16+j ----
    for (int i = tid; i < 64 * 512; i += TPB) {
        int k = i & 511, n = i >> 9;
        int g = n >> 4, j = n & 15;
        float v = R[(size_t)k * FOURU + g * UNITS + u0 + j];
        __nv_bfloat16 hb = __float2bfloat16(v);
        __nv_bfloat16 lb = __float2bfloat16(v - __bfloat162float(hb));
        Bhi[n * 520 + k] = hb;
        Blo[n * 520 + k] = lb;
    }

    // ---- xz staging map: thread -> (pb, pg, pq) ----------------------------
    const int pb = tid >> 4, pg = (tid >> 2) & 3, pq = tid & 3;
    const float* xz_thread = g_xz + (size_t)(b0 + pb) * TSTEPS * FOURU
                             + pg * UNITS + u0 + pq * 4;
    {
        float4 v = __ldcs((const float4*)xz_thread);
        float vv[4] = {v.x, v.y, v.z, v.w};
#pragma unroll
        for (int j = 0; j < 4; j++)
            xzs[pg * 272 + (pq * 4 + j) * 17 + pb] = vv[j];
    }
    __syncthreads();

    // ---- lane-invariant LDSM addresses -------------------------------------
    const int khalf = wid >> 2, npair = wid & 3;
    const int aRow = (lane & 7) + ((lane >> 3) & 1) * 8;
    const int aKof = ((lane >> 4) & 1) * 16;            // bytes
    const uint32_t aHiAddr = smem_u32(smc + SM_AHI) + aRow * 1040 + aKof;
    const uint32_t aLoAddr = smem_u32(smc + SM_ALO) + aRow * 1040 + aKof;
    const int bRow = npair * 16 + ((lane >> 4) & 1) * 8 + (lane & 7);
    const int bKof = ((lane >> 3) & 1) * 16;
    const uint32_t bHiAddr = smem_u32(smc + SM_BHI) + bRow * 1040 + bKof;
    const uint32_t bLoAddr = smem_u32(smc + SM_BLO) + bRow * 1040 + bKof;

    // ---- preload this warp's B-hi fragments into registers (time-invariant)
    uint4 Bh[16];
#pragma unroll
    for (int i = 0; i < 16; i++)
        LDSM4(Bh[i], bHiAddr + (khalf * 16 + i) * 32);

    // A-staging map: b = tid>>4, 8 chunks of 4 floats at u = (tid&15)*4+q*64
    const int sb = tid >> 4, su = (tid & 15) * 4;
    // gates map (coalesced h writeback): b = tid>>4, u = tid&15
    const int b_l = tid >> 4, j_l = tid & 15;

    unsigned* arrive = &g_arrive[bg * 32];
    unsigned* gen    = &g_gen[bg * 32];

    float c_state = 0.f;

    for (int t = 0; t < TSTEPS; t++) {
        const int par = t & 1;
        float4 xnext = make_float4(0.f, 0.f, 0.f, 0.f);
        if (t + 1 < TSTEPS)
            xnext = __ldcs((const float4*)(xz_thread + (size_t)(t + 1) * FOURU));

        // ---- stage A = h(t)[16 b][512 k] as split bf16 ----
        const float* hsrc = &g_h[par][b0 + sb][0];
#pragma unroll
        for (int q = 0; q < 8; q++) {
            int u = su + q * 64;
            float4 v = __ldcg((const float4*)(hsrc + u));
            uint32_t h01, h23, l01, l23;
            asm("cvt.rn.bf16x2.f32 %0, %1, %2;" : "=r"(h01) : "f"(v.y), "f"(v.x));
            asm("cvt.rn.bf16x2.f32 %0, %1, %2;" : "=r"(h23) : "f"(v.w), "f"(v.z));
            float f0 = __uint_as_float(h01 << 16);
            float f1 = __uint_as_float(h01 & 0xffff0000u);
            float f2 = __uint_as_float(h23 << 16);
            float f3 = __uint_as_float(h23 & 0xffff0000u);
            asm("cvt.rn.bf16x2.f32 %0, %1, %2;"
                : "=r"(l01) : "f"(v.y - f1), "f"(v.x - f0));
            asm("cvt.rn.bf16x2.f32 %0, %1, %2;"
                : "=r"(l23) : "f"(v.w - f3), "f"(v.z - f2));
            int w = sb * 260 + u / 2;
            AhiW[w] = h01; AhiW[w + 1] = h23;
            AloW[w] = l01; AloW[w + 1] = l23;
        }
        __syncthreads();

        // ---- MMA: n-tiles {2*npair, 2*npair+1}, k-half khalf ----
        float acc0[4] = {0.f, 0.f, 0.f, 0.f};
        float acc1[4] = {0.f, 0.f, 0.f, 0.f};
#pragma unroll
        for (int i = 0; i < 16; i++) {
            uint32_t ofs = (khalf * 16 + i) * 32;
            uint4 ah, al, bl;
            LDSM4(ah, aHiAddr + ofs);
            LDSM4(al, aLoAddr + ofs);
            LDSM4(bl, bLoAddr + ofs);
            MMA16816(acc0, ah, Bh[i].x, Bh[i].y);
            MMA16816(acc1, ah, Bh[i].z, Bh[i].w);
            MMA16816(acc0, ah, bl.x, bl.y);
            MMA16816(acc1, ah, bl.z, bl.w);
            MMA16816(acc0, al, Bh[i].x, Bh[i].y);
            MMA16816(acc1, al, Bh[i].z, Bh[i].w);
        }

        // ---- both halves write partial z to their own buffer ----
        {
            float* zb = zbuf + khalf * 1088;
            int ra = lane >> 2, cb = (lane & 3) * 2;
            int n0 = npair * 16 + cb, n1 = npair * 16 + 8 + cb;
            *(float2*)&zb[ra * 68 + n0]       = make_float2(acc0[0], acc0[1]);
            *(float2*)&zb[(ra + 8) * 68 + n0] = make_float2(acc0[2], acc0[3]);
            *(float2*)&zb[ra * 68 + n1]       = make_float2(acc1[0], acc1[1]);
            *(float2*)&zb[(ra + 8) * 68 + n1] = make_float2(acc1[2], acc1[3]);
        }
        __syncthreads();

        // ---- gates: thread (b_l = tid>>4, j_l = tid&15) ----
        {
            const float* z0 = zbuf + b_l * 68 + j_l;
            const float* z1 = zbuf + 1088 + b_l * 68 + j_l;
            const float* xb = xzs + par * 1088 + j_l * 17 + b_l;
            float zv1 = z0[0]  + z1[0]  + xb[0];
            float zv2 = z0[16] + z1[16] + xb[272];
            float zv3 = z0[32] + z1[32] + xb[544];
            float zv4 = z0[48] + z1[48] + xb[816];
            float v1 = ftanh(zv1);
            float v2 = fsig(zv2);
            float v3 = fsig(zv3);
            float v4 = fsig(zv4);
            c_state = v1 * v2 + v3 * c_state;
            float hnew = v4 * ftanh(c_state);
            __stcg(&g_h[par ^ 1][b0 + b_l][u0 + j_l], hnew);
        }

        // ---- barrier: arrive early, stage xz, poll ----
        __syncthreads();
        if (tid == 0) {
            unsigned prev = atom_add_acqrel(arrive, 1u);
            if ((prev & 31u) == 31u)
                st_release(gen, (unsigned)(t + 1));
        }
        if (t + 1 < TSTEPS) {
            float vv[4] = {xnext.x, xnext.y, xnext.z, xnext.w};
            float* dst = xzs + ((t + 1) & 1) * 1088;
#pragma unroll
            for (int j = 0; j < 4; j++)
                dst[pg * 272 + (pq * 4 + j) * 17 + pb] = vv[j];
        }
        if (tid == 0) {
            while (ld_acquire(gen) < (unsigned)(t + 1)) { }
        }
        __syncthreads();
    }
}

// ---- final dense + softmax --------------------------------------------------
__global__ void fc_softmax(const float* __restrict__ fc_w,
                           const float* __restrict__ fc_b,
                           float* __restrict__ out)
{
    const int b = blockIdx.x;
    const int l = threadIdx.x;
    float a0 = 0.f, a1 = 0.f, a2 = 0.f, a3 = 0.f;
    const float* hg = &g_h[0][b][0];   // t=1023 wrote parity 0
    for (int k = l * 16; k < l * 16 + 16; k += 4) {
        float4 hv = *(const float4*)(hg + k);
        float hx[4] = {hv.x, hv.y, hv.z, hv.w};
#pragma unroll
        for (int q = 0; q < 4; q++) {
            float4 wv = *(const float4*)&fc_w[(k + q) * 4];
            a0 += hx[q] * wv.x; a1 += hx[q] * wv.y;
            a2 += hx[q] * wv.z; a3 += hx[q] * wv.w;
        }
    }
#pragma unroll
    for (int o = 16; o > 0; o >>= 1) {
        a0 += __shfl_down_sync(0xffffffffu, a0, o);
        a1 += __shfl_down_sync(0xffffffffu, a1, o);
        a2 += __shfl_down_sync(0xffffffffu, a2, o);
        a3 += __shfl_down_sync(0xffffffffu, a3, o);
    }
    if (l == 0) {
        float z0 = a0 + fc_b[0], z1 = a1 + fc_b[1];
        float z2 = a2 + fc_b[2], z3 = a3 + fc_b[3];
        float m = fmaxf(fmaxf(z0, z1), fmaxf(z2, z3));
        float e0 = __expf(z0 - m), e1 = __expf(z1 - m);
        float e2 = __expf(z2 - m), e3 = __expf(z3 - m);
        float inv = __fdividef(1.f, e0 + e1 + e2 + e3);
        out[b * 4 + 0] = e0 * inv;
        out[b * 4 + 1] = e1 * inv;
        out[b * 4 + 2] = e2 * inv;
        out[b * 4 + 3] = e3 * inv;
    }
}

// ---------------------------------------------------------------------------
extern "C" void kernel_launch(void* const* d_in, const int* in_sizes, int n_in,
                              void* d_out, int out_size)
{
    const float* tx      = (const float*)d_in[0];
    const float* kernelW = (const float*)d_in[1];
    const float* R       = (const float*)d_in[2];
    const float* bias    = (const float*)d_in[3];
    const float* fc_w    = (const float*)d_in[4];
    const float* fc_b    = (const float*)d_in[5];
    float* out           = (float*)d_out;

    cudaFuncSetAttribute(lstm_recur,
                         cudaFuncAttributeMaxDynamicSharedMemorySize, SM_BYTES);

    init_kernel<<<(2 * BATCH * UNITS + 255) / 256, 256>>>();
    prep_A<<<16384, 256>>>(tx);
    prep_W<<<256, 256>>>(kernelW);
    gemm_mma<<<dim3(16, 512), 256>>>(bias);
    lstm_recur<<<NCTA, TPB, SM_BYTES>>>(R);
    fc_softmax<<<BATCH, 32>>>(fc_w, fc_b, out);
    (void)in_sizes; (void)n_in; (void)out_size;
}